// round 13
// baseline (speedup 1.0000x reference)
#include <cuda_runtime.h>
#include <math.h>
#include <stdint.h>

// ---------------------------------------------------------------------------
// Problem constants
// ---------------------------------------------------------------------------
#define NUM_EMBED   512
#define EMBED_DIM   64
#define BATCH       4
#define SPATIAL     32768           // 32*32*32
#define N_TOKENS    (BATCH*SPATIAL) // 131072
#define Q_ELEMS     (BATCH*EMBED_DIM*SPATIAL) // 8388608

// Output offsets (tuple flattened, float32)
#define OFF_LOSS      0
#define OFF_Q         1
#define OFF_PERP      (OFF_Q + Q_ELEMS)
#define OFF_IDX       (OFF_PERP + 1)
#define OFF_NEWEMBED  (OFF_IDX + N_TOKENS)
#define OFF_CS        (OFF_NEWEMBED + NUM_EMBED*EMBED_DIM)
#define OFF_EA        (OFF_CS + NUM_EMBED)

#define DECAY           0.99f
#define ONE_MINUS_DECAY 0.01f
#define COMMIT_COST     0.25f
#define LAPLACE_ALPHA   1e-5f

// Virtual-K GEMM layout: K = 192 = 24 k-tiles of 8.
//   k in [0,64):    A = xhi[k],     B = ehi[k]
//   k in [64,128):  A = xlo[k-64],  B = ehi[k-64]
//   k in [128,192): A = xhi[k-128], B = elo[k-128]
// Conflict-free banking: QS mod 32 == 24 -> q spreads {0,8,16,24};
//                        PN mod 32 == 4  -> g (2 per phase) spreads {0,4}.
// Together the 8 lanes of each LDS.128 phase cover all 32 banks.
#define PN  228    // packed B row stride in floats (224 used + 4 pad)
#define QS  56     // per-q stride within a row (48 used + 8 pad)
#define CC  64     // codes per streamed chunk
#define NCHUNK (NUM_EMBED / CC)          // 8
#define CHUNK_BYTES (CC * PN * 4)        // 58368

// ---------------------------------------------------------------------------
// Scratch (device globals — no allocations allowed)
// ---------------------------------------------------------------------------
__device__ float  g_counts[NUM_EMBED];
__device__ float  g_dw[NUM_EMBED * EMBED_DIM];
__device__ double g_loss;
__device__ float  g_halfn[NUM_EMBED];                       // 0.5*||e||^2 exact
__device__ __align__(16) float g_bpack[NUM_EMBED * PN];     // packed tf32 B

// ---------------------------------------------------------------------------
// Helpers (baseline sm_80+ PTX only — no 'a'-suffix features)
// ---------------------------------------------------------------------------
__device__ __forceinline__ uint32_t smem_u32(const void* p) {
    uint32_t a;
    asm("{ .reg .u64 t; cvta.to.shared.u64 t, %1; cvt.u32.u64 %0, t; }"
        : "=r"(a) : "l"(p));
    return a;
}
__device__ __forceinline__ float tf32f(float x) {
    uint32_t u;
    asm("cvt.rna.tf32.f32 %0, %1;" : "=r"(u) : "f"(x));
    return __uint_as_float(u);
}
__device__ __forceinline__ void mma8(float d[4],
                                     uint32_t a0, uint32_t a1, uint32_t a2, uint32_t a3,
                                     uint32_t b0, uint32_t b1) {
    asm volatile(
        "mma.sync.aligned.m16n8k8.row.col.f32.tf32.tf32.f32 "
        "{%0,%1,%2,%3}, {%4,%5,%6,%7}, {%8,%9}, {%0,%1,%2,%3};"
        : "+f"(d[0]), "+f"(d[1]), "+f"(d[2]), "+f"(d[3])
        : "r"(a0), "r"(a1), "r"(a2), "r"(a3), "r"(b0), "r"(b1));
}
#define CP_ASYNC16(dst_smem_u32, src_gptr) \
    asm volatile("cp.async.cg.shared.global [%0], [%1], 16;" \
                 :: "r"(dst_smem_u32), "l"(src_gptr) : "memory")
#define CP_COMMIT() asm volatile("cp.async.commit_group;" ::: "memory")
#define CP_WAIT1()  asm volatile("cp.async.wait_group 1;" ::: "memory")

// ---------------------------------------------------------------------------
// Prep kernels
// ---------------------------------------------------------------------------
__global__ void vq_zero_kernel() {
    int i = blockIdx.x * blockDim.x + threadIdx.x;
    if (i < NUM_EMBED * EMBED_DIM) g_dw[i] = 0.0f;
    if (i < NUM_EMBED)             g_counts[i] = 0.0f;
    if (i == 0)                    g_loss = 0.0;
}

// Pack B in exact fragment-consumption order:
// row n (code), offset = q*QS + u*4 + kt1*2 + p, where ktile = 2u+kt1,
// virtual k = ktile*8 + q + p*4.
__global__ void vq_pack_b_kernel(const float* __restrict__ embed) {
    int idx = blockIdx.x * blockDim.x + threadIdx.x;   // over 512*192
    if (idx >= NUM_EMBED * 192) return;
    int n = idx / 192, r = idx % 192;
    int q = r / 48, t = r % 48;
    int u = t >> 2, kt1 = (t >> 1) & 1, p = t & 1;
    int ktile = 2 * u + kt1;
    int k = ktile * 8 + q + p * 4;                     // virtual k 0..191
    int c = k & 63;
    float e  = embed[n * EMBED_DIM + c];
    float hi = tf32f(e);
    float v  = (k < 128) ? hi : tf32f(e - hi);
    g_bpack[n * PN + q * QS + t] = v;
}

__global__ void __launch_bounds__(NUM_EMBED)
vq_halfn_kernel(const float* __restrict__ embed) {
    int k = threadIdx.x;
    const float* row = embed + k * EMBED_DIM;
    float s = 0.0f;
    #pragma unroll
    for (int c = 0; c < EMBED_DIM; c++) s = fmaf(row[c], row[c], s);
    g_halfn[k] = 0.5f * s;
}

// ---------------------------------------------------------------------------
// Main kernel: tf32 3-split mma.sync distance GEMM + argmin + exact epilogue
// Grid: 512 CTAs x 256 threads; 256 tokens/CTA = 8 warps x 2 Mtiles x 16.
// 4 accumulator chains per thread (2 Mtiles x 2 n-groups); B reads amortized
// over both Mtiles; conflict-free LDS banking.
// ---------------------------------------------------------------------------
#define MAIN_THREADS 256
#define TPC          256
#define MAIN_CTAS    (N_TOKENS / TPC)   // 512

// smem layout
#define SM_HALFN 0        // 512 f32 = 2048 B
#define SM_BESTK 2048     // 256 i32 = 1024 B
#define SM_BUF   4096     // 2 x CHUNK_BYTES
#define SMEM_TOTAL (SM_BUF + 2 * CHUNK_BYTES)   // 120832

extern __shared__ char smem_raw[];

__global__ void __launch_bounds__(MAIN_THREADS, 1)
vq_main_kernel(const float* __restrict__ inputs,
               const float* __restrict__ embed,
               float* __restrict__ out)
{
    const uint32_t sb = smem_u32(smem_raw);
    const int tid  = threadIdx.x;
    const int wid  = tid >> 5;
    const int lane = tid & 31;
    const int q    = lane & 3;    // k-index class / D-col pair
    const int g    = lane >> 2;   // row-in-Mtile / code-in-group

    float* sm_halfn = (float*)(smem_raw + SM_HALFN);
    int*   sm_bestk = (int*)(smem_raw + SM_BESTK);

    // ---- start streaming B chunks 0 and 1 immediately ----
    {
        const char* src = (const char*)g_bpack;
        for (int off = tid * 16; off < CHUNK_BYTES; off += MAIN_THREADS * 16)
            CP_ASYNC16(sb + SM_BUF + off, src + off);
        CP_COMMIT();
        for (int off = tid * 16; off < CHUNK_BYTES; off += MAIN_THREADS * 16)
            CP_ASYNC16(sb + SM_BUF + CHUNK_BYTES + off, src + CHUNK_BYTES + off);
        CP_COMMIT();
    }

    // halfn -> smem
    for (int k = tid; k < NUM_EMBED; k += MAIN_THREADS)
        sm_halfn[k] = g_halfn[k];

    // ---- A fragments: 2 Mtiles per warp, hi+lo (128 regs) ----
    const int n0 = blockIdx.x * TPC;
    const int bb = n0 >> 15;
    const int s0 = n0 & (SPATIAL - 1);
    const float* xbase = inputs + (size_t)bb * (EMBED_DIM * SPATIAL) + s0;

    uint32_t ahi[2][32], alo[2][32];
    #pragma unroll
    for (int m = 0; m < 2; m++) {
        #pragma unroll
        for (int h = 0; h < 2; h++) {
            const int tok = wid * 32 + m * 16 + h * 8 + g;
            #pragma unroll
            for (int kt = 0; kt < 8; kt++) {
                #pragma unroll
                for (int pp = 0; pp < 2; pp++) {
                    const int c = kt * 8 + q + pp * 4;
                    const float x  = xbase[(size_t)c * SPATIAL + tok];
                    const float hi = tf32f(x);
                    const float lo = tf32f(x - hi);
                    ahi[m][h * 16 + kt * 2 + pp] = __float_as_uint(hi);
                    alo[m][h * 16 + kt * 2 + pp] = __float_as_uint(lo);
                }
            }
        }
    }

    // per-thread argmin state: [m][h] -> token row wid*32+m*16+h*8+g
    float best[2][2] = {{3.4e38f, 3.4e38f}, {3.4e38f, 3.4e38f}};
    int   bidx[2][2] = {{0, 0}, {0, 0}};

    // ---- chunk loop ----
    #pragma unroll 1
    for (int ch = 0; ch < NCHUNK; ch++) {
        CP_WAIT1();
        __syncthreads();
        const float* B = (const float*)(smem_raw + SM_BUF + (ch & 1) * CHUNK_BYTES);

        #pragma unroll 1
        for (int ntp = 0; ntp < 4; ntp++) {          // pairs of 8-code groups
            float d0a[4] = {0.f, 0.f, 0.f, 0.f};     // Mtile0 x ngroup a
            float d1a[4] = {0.f, 0.f, 0.f, 0.f};     // Mtile1 x ngroup a
            float d0b[4] = {0.f, 0.f, 0.f, 0.f};     // Mtile0 x ngroup b
            float d1b[4] = {0.f, 0.f, 0.f, 0.f};     // Mtile1 x ngroup b
            const float* browa = B + (size_t)(ntp * 16 + g)     * PN + q * QS;
            const float* browb = B + (size_t)(ntp * 16 + 8 + g) * PN + q * QS;

            #pragma unroll
            for (int u = 0; u < 12; u++) {
                const float4 bva = *(const float4*)(browa + u * 4);
                const float4 bvb = *(const float4*)(browb + u * 4);
                #pragma unroll
                for (int kk = 0; kk < 2; kk++) {
                    const int kt = 2 * u + kk;       // 0..23, compile-time
                    const uint32_t ba0 = __float_as_uint(kk ? bva.z : bva.x);
                    const uint32_t ba1 = __float_as_uint(kk ? bva.w : bva.y);
                    const uint32_t bb0 = __float_as_uint(kk ? bvb.z : bvb.x);
                    const uint32_t bb1 = __float_as_uint(kk ? bvb.w : bvb.y);
                    const int i0 = (kt & 7) * 2;
                    const bool useLo = (kt >= 8) && (kt < 16);
                    const uint32_t a00 = useLo ? alo[0][i0]      : ahi[0][i0];
                    const uint32_t a01 = useLo ? alo[0][16 + i0] : ahi[0][16 + i0];
                    const uint32_t a02 = useLo ? alo[0][i0 + 1]  : ahi[0][i0 + 1];
                    const uint32_t a03 = useLo ? alo[0][17 + i0] : ahi[0][17 + i0];
                    const uint32_t a10 = useLo ? alo[1][i0]      : ahi[1][i0];
                    const uint32_t a11 = useLo ? alo[1][16 + i0] : ahi[1][16 + i0];
                    const uint32_t a12 = useLo ? alo[1][i0 + 1]  : ahi[1][i0 + 1];
                    const uint32_t a13 = useLo ? alo[1][17 + i0] : ahi[1][17 + i0];
                    mma8(d0a, a00, a01, a02, a03, ba0, ba1);
                    mma8(d1a, a10, a11, a12, a13, ba0, ba1);
                    mma8(d0b, a00, a01, a02, a03, bb0, bb1);
                    mma8(d1b, a10, a11, a12, a13, bb0, bb1);
                }
            }

            // fold; codes ascend across groups -> strict < keeps first min
            const int kba = ch * CC + ntp * 16;
            const int kbb = kba + 8;
            const float2 hna = *(const float2*)(sm_halfn + kba + 2 * q);
            const float2 hnb = *(const float2*)(sm_halfn + kbb + 2 * q);
            const int ca0 = kba + 2 * q, ca1 = ca0 + 1;
            const int cb0 = kbb + 2 * q, cb1 = cb0 + 1;
            float dd;
            dd = hna.x - d0a[0]; if (dd < best[0][0]) { best[0][0] = dd; bidx[0][0] = ca0; }
            dd = hna.y - d0a[1]; if (dd < best[0][0]) { best[0][0] = dd; bidx[0][0] = ca1; }
            dd = hna.x - d0a[2]; if (dd < best[0][1]) { best[0][1] = dd; bidx[0][1] = ca0; }
            dd = hna.y - d0a[3]; if (dd < best[0][1]) { best[0][1] = dd; bidx[0][1] = ca1; }
            dd = hna.x - d1a[0]; if (dd < best[1][0]) { best[1][0] = dd; bidx[1][0] = ca0; }
            dd = hna.y - d1a[1]; if (dd < best[1][0]) { best[1][0] = dd; bidx[1][0] = ca1; }
            dd = hna.x - d1a[2]; if (dd < best[1][1]) { best[1][1] = dd; bidx[1][1] = ca0; }
            dd = hna.y - d1a[3]; if (dd < best[1][1]) { best[1][1] = dd; bidx[1][1] = ca1; }
            dd = hnb.x - d0b[0]; if (dd < best[0][0]) { best[0][0] = dd; bidx[0][0] = cb0; }
            dd = hnb.y - d0b[1]; if (dd < best[0][0]) { best[0][0] = dd; bidx[0][0] = cb1; }
            dd = hnb.x - d0b[2]; if (dd < best[0][1]) { best[0][1] = dd; bidx[0][1] = cb0; }
            dd = hnb.y - d0b[3]; if (dd < best[0][1]) { best[0][1] = dd; bidx[0][1] = cb1; }
            dd = hnb.x - d1b[0]; if (dd < best[1][0]) { best[1][0] = dd; bidx[1][0] = cb0; }
            dd = hnb.y - d1b[1]; if (dd < best[1][0]) { best[1][0] = dd; bidx[1][0] = cb1; }
            dd = hnb.x - d1b[2]; if (dd < best[1][1]) { best[1][1] = dd; bidx[1][1] = cb0; }
            dd = hnb.y - d1b[3]; if (dd < best[1][1]) { best[1][1] = dd; bidx[1][1] = cb1; }
        }

        __syncthreads();   // all warps done with buf[ch&1] before refill
        {
            const int nxt = ch + 2;
            if (nxt < NCHUNK) {
                const char* src = (const char*)g_bpack + (size_t)nxt * CHUNK_BYTES;
                for (int off = tid * 16; off < CHUNK_BYTES; off += MAIN_THREADS * 16)
                    CP_ASYNC16(sb + SM_BUF + (ch & 1) * CHUNK_BYTES + off, src + off);
            }
            CP_COMMIT();   // commit every iteration (possibly empty) to keep counts
        }
    }

    // ---- quad reduction (lanes q=0..3 hold disjoint code subsets) ----
    #pragma unroll
    for (int m = 0; m < 2; m++) {
        #pragma unroll
        for (int h = 0; h < 2; h++) {
            float b = best[m][h];
            int   bi = bidx[m][h];
            #pragma unroll
            for (int delta = 1; delta <= 2; delta <<= 1) {
                const float ob = __shfl_down_sync(0xffffffffu, b, delta, 4);
                const int   oi = __shfl_down_sync(0xffffffffu, bi, delta, 4);
                if (ob < b || (ob == b && oi < bi)) { b = ob; bi = oi; }
            }
            if (q == 0)
                sm_bestk[wid * 32 + m * 16 + h * 8 + g] = bi;
        }
    }
    __syncthreads();

    // ---- exact fp32 epilogue: one token per thread (bit-identical to R3) ----
    {
        const int n = n0 + tid;
        const int k = sm_bestk[tid];
        out[OFF_IDX + n] = (float)k;
        atomicAdd(&g_counts[k], 1.0f);

        const float* er  = embed + (size_t)k * EMBED_DIM;
        const float* xin = xbase + tid;
        float* qout = out + OFF_Q + (size_t)bb * (EMBED_DIM * SPATIAL) + s0 + tid;
        float* dwr  = g_dw + (size_t)k * EMBED_DIM;

        float lsum = 0.0f;
        #pragma unroll 8
        for (int c = 0; c < EMBED_DIM; c++) {
            const float e = er[c];
            const float x = xin[(size_t)c * SPATIAL];
            const float d = e - x;                 // quantized_cf - inputs
            lsum = fmaf(d, d, lsum);
            qout[(size_t)c * SPATIAL] = x + d;     // straight-through rounding
            atomicAdd(&dwr[c], x);
        }
        double la = (double)lsum;
        #pragma unroll
        for (int off = 16; off > 0; off >>= 1)
            la += __shfl_down_sync(0xffffffffu, la, off);
        if (lane == 0) atomicAdd(&g_loss, la);
    }
}

// ---------------------------------------------------------------------------
// Finalize: EMA update, Laplace smoothing, perplexity, loss
// ---------------------------------------------------------------------------
__global__ void __launch_bounds__(NUM_EMBED)
vq_finalize_kernel(const float* __restrict__ embed_avg,
                   const float* __restrict__ cluster_size,
                   float* __restrict__ out)
{
    __shared__ float  s_smoothed[NUM_EMBED];
    __shared__ double s_red[NUM_EMBED];

    const int t = threadIdx.x;

    const float cnt = g_counts[t];
    const float ncs = cluster_size[t] * DECAY + ONE_MINUS_DECAY * cnt;
    out[OFF_CS + t] = ncs;

    s_red[t] = (double)ncs;
    __syncthreads();
    #pragma unroll
    for (int off = NUM_EMBED / 2; off > 0; off >>= 1) {
        if (t < off) s_red[t] += s_red[t + off];
        __syncthreads();
    }
    const float nf = (float)s_red[0];
    __syncthreads();

    s_smoothed[t] = nf * ((ncs + LAPLACE_ALPHA) / (nf + NUM_EMBED * LAPLACE_ALPHA));

    const float p = cnt / (float)N_TOKENS;
    s_red[t] = (double)(p * logf(p + 1e-10f));
    __syncthreads();
    #pragma unroll
    for (int off = NUM_EMBED / 2; off > 0; off >>= 1) {
        if (t < off) s_red[t] += s_red[t + off];
        __syncthreads();
    }
    if (t == 0) {
        out[OFF_PERP] = expf(-(float)s_red[0]);
        out[OFF_LOSS] = COMMIT_COST * (float)(g_loss / (double)Q_ELEMS);
    }
    __syncthreads();

    for (int i = t; i < NUM_EMBED * EMBED_DIM; i += NUM_EMBED) {
        const float ea = embed_avg[i] * DECAY + ONE_MINUS_DECAY * g_dw[i];
        out[OFF_EA + i]       = ea;
        out[OFF_NEWEMBED + i] = ea / s_smoothed[i >> 6];
    }
}

// ---------------------------------------------------------------------------
// Launch
// ---------------------------------------------------------------------------
extern "C" void kernel_launch(void* const* d_in, const int* in_sizes, int n_in,
                              void* d_out, int out_size)
{
    const float* inputs       = (const float*)d_in[0];
    const float* embed        = (const float*)d_in[1];
    const float* embed_avg    = (const float*)d_in[2];
    const float* cluster_size = (const float*)d_in[3];
    float* out = (float*)d_out;

    cudaFuncSetAttribute(vq_main_kernel,
                         cudaFuncAttributeMaxDynamicSharedMemorySize, SMEM_TOTAL);

    vq_zero_kernel<<<(NUM_EMBED * EMBED_DIM + 255) / 256, 256>>>();
    vq_pack_b_kernel<<<(NUM_EMBED * 192 + 255) / 256, 256>>>(embed);
    vq_halfn_kernel<<<1, NUM_EMBED>>>(embed);
    vq_main_kernel<<<MAIN_CTAS, MAIN_THREADS, SMEM_TOTAL>>>(inputs, embed, out);
    vq_finalize_kernel<<<1, NUM_EMBED>>>(embed_avg, cluster_size, out);
}

// round 14
// speedup vs baseline: 1.0182x; 1.0182x over previous
#include <cuda_runtime.h>
#include <math.h>
#include <stdint.h>

// ---------------------------------------------------------------------------
// Problem constants
// ---------------------------------------------------------------------------
#define NUM_EMBED   512
#define EMBED_DIM   64
#define BATCH       4
#define SPATIAL     32768           // 32*32*32
#define N_TOKENS    (BATCH*SPATIAL) // 131072
#define Q_ELEMS     (BATCH*EMBED_DIM*SPATIAL) // 8388608

// Output offsets (tuple flattened, float32)
#define OFF_LOSS      0
#define OFF_Q         1
#define OFF_PERP      (OFF_Q + Q_ELEMS)
#define OFF_IDX       (OFF_PERP + 1)
#define OFF_NEWEMBED  (OFF_IDX + N_TOKENS)
#define OFF_CS        (OFF_NEWEMBED + NUM_EMBED*EMBED_DIM)
#define OFF_EA        (OFF_CS + NUM_EMBED)

#define DECAY           0.99f
#define ONE_MINUS_DECAY 0.01f
#define COMMIT_COST     0.25f
#define LAPLACE_ALPHA   1e-5f

// Virtual-K GEMM layout: K = 192 = 24 k-tiles of 8.
//   k in [0,64):    A = xhi[k],     B = ehi[k]
//   k in [64,128):  A = xlo[k-64],  B = ehi[k-64]
//   k in [128,192): A = xhi[k-128], B = elo[k-128]
// Conflict-free banking: QS mod 32 == 24 -> q spreads {0,8,16,24};
//                        PN mod 32 == 4  -> g (2 per phase) spreads {0,4}.
// Together the 8 lanes of each LDS.128 phase cover all 32 banks.
#define PN  228    // packed B row stride in floats (224 used + 4 pad)
#define QS  56     // per-q stride within a row (48 used + 8 pad)
#define CC  64     // codes per streamed chunk
#define NCHUNK (NUM_EMBED / CC)          // 8
#define CHUNK_BYTES (CC * PN * 4)        // 58368

// ---------------------------------------------------------------------------
// Scratch (device globals — no allocations allowed)
// ---------------------------------------------------------------------------
__device__ float  g_counts[NUM_EMBED];
__device__ float  g_dw[NUM_EMBED * EMBED_DIM];
__device__ double g_loss;
__device__ float  g_halfn[NUM_EMBED];                       // 0.5*||e||^2 exact
__device__ __align__(16) float g_bpack[NUM_EMBED * PN];     // packed tf32 B

// ---------------------------------------------------------------------------
// Helpers (baseline sm_80+ PTX only — no 'a'-suffix features)
// ---------------------------------------------------------------------------
__device__ __forceinline__ uint32_t smem_u32(const void* p) {
    uint32_t a;
    asm("{ .reg .u64 t; cvta.to.shared.u64 t, %1; cvt.u32.u64 %0, t; }"
        : "=r"(a) : "l"(p));
    return a;
}
__device__ __forceinline__ float tf32f(float x) {
    uint32_t u;
    asm("cvt.rna.tf32.f32 %0, %1;" : "=r"(u) : "f"(x));
    return __uint_as_float(u);
}
__device__ __forceinline__ void mma8(float d[4],
                                     uint32_t a0, uint32_t a1, uint32_t a2, uint32_t a3,
                                     uint32_t b0, uint32_t b1) {
    asm volatile(
        "mma.sync.aligned.m16n8k8.row.col.f32.tf32.tf32.f32 "
        "{%0,%1,%2,%3}, {%4,%5,%6,%7}, {%8,%9}, {%0,%1,%2,%3};"
        : "+f"(d[0]), "+f"(d[1]), "+f"(d[2]), "+f"(d[3])
        : "r"(a0), "r"(a1), "r"(a2), "r"(a3), "r"(b0), "r"(b1));
}
#define CP_ASYNC16(dst_smem_u32, src_gptr) \
    asm volatile("cp.async.cg.shared.global [%0], [%1], 16;" \
                 :: "r"(dst_smem_u32), "l"(src_gptr) : "memory")
#define CP_COMMIT() asm volatile("cp.async.commit_group;" ::: "memory")
#define CP_WAIT1()  asm volatile("cp.async.wait_group 1;" ::: "memory")

// ---------------------------------------------------------------------------
// Prep kernels
// ---------------------------------------------------------------------------
__global__ void vq_zero_kernel() {
    int i = blockIdx.x * blockDim.x + threadIdx.x;
    if (i < NUM_EMBED * EMBED_DIM) g_dw[i] = 0.0f;
    if (i < NUM_EMBED)             g_counts[i] = 0.0f;
    if (i == 0)                    g_loss = 0.0;
}

// Pack B in exact fragment-consumption order:
// row n (code), offset = q*QS + u*4 + kt1*2 + p, where ktile = 2u+kt1,
// virtual k = ktile*8 + q + p*4.
__global__ void vq_pack_b_kernel(const float* __restrict__ embed) {
    int idx = blockIdx.x * blockDim.x + threadIdx.x;   // over 512*192
    if (idx >= NUM_EMBED * 192) return;
    int n = idx / 192, r = idx % 192;
    int q = r / 48, t = r % 48;
    int u = t >> 2, kt1 = (t >> 1) & 1, p = t & 1;
    int ktile = 2 * u + kt1;
    int k = ktile * 8 + q + p * 4;                     // virtual k 0..191
    int c = k & 63;
    float e  = embed[n * EMBED_DIM + c];
    float hi = tf32f(e);
    float v  = (k < 128) ? hi : tf32f(e - hi);
    g_bpack[n * PN + q * QS + t] = v;
}

__global__ void __launch_bounds__(NUM_EMBED)
vq_halfn_kernel(const float* __restrict__ embed) {
    int k = threadIdx.x;
    const float* row = embed + k * EMBED_DIM;
    float s = 0.0f;
    #pragma unroll
    for (int c = 0; c < EMBED_DIM; c++) s = fmaf(row[c], row[c], s);
    g_halfn[k] = 0.5f * s;
}

// ---------------------------------------------------------------------------
// Main kernel: tf32 3-split mma.sync distance GEMM + argmin + exact epilogue
// Grid: 512 CTAs x 256 threads; 256 tokens/CTA = 8 warps x 2 Mtiles x 16.
// 4 accumulator chains per thread (2 Mtiles x 2 n-groups); B reads amortized
// over both Mtiles; conflict-free LDS banking.
// ---------------------------------------------------------------------------
#define MAIN_THREADS 256
#define TPC          256
#define MAIN_CTAS    (N_TOKENS / TPC)   // 512

// smem layout
#define SM_HALFN 0        // 512 f32 = 2048 B
#define SM_BESTK 2048     // 256 i32 = 1024 B
#define SM_BUF   4096     // 2 x CHUNK_BYTES
#define SMEM_TOTAL (SM_BUF + 2 * CHUNK_BYTES)   // 120832

extern __shared__ char smem_raw[];

__global__ void __launch_bounds__(MAIN_THREADS, 1)
vq_main_kernel(const float* __restrict__ inputs,
               const float* __restrict__ embed,
               float* __restrict__ out)
{
    const uint32_t sb = smem_u32(smem_raw);
    const int tid  = threadIdx.x;
    const int wid  = tid >> 5;
    const int lane = tid & 31;
    const int q    = lane & 3;    // k-index class / D-col pair
    const int g    = lane >> 2;   // row-in-Mtile / code-in-group

    float* sm_halfn = (float*)(smem_raw + SM_HALFN);
    int*   sm_bestk = (int*)(smem_raw + SM_BESTK);

    // ---- start streaming B chunks 0 and 1 immediately ----
    {
        const char* src = (const char*)g_bpack;
        for (int off = tid * 16; off < CHUNK_BYTES; off += MAIN_THREADS * 16)
            CP_ASYNC16(sb + SM_BUF + off, src + off);
        CP_COMMIT();
        for (int off = tid * 16; off < CHUNK_BYTES; off += MAIN_THREADS * 16)
            CP_ASYNC16(sb + SM_BUF + CHUNK_BYTES + off, src + CHUNK_BYTES + off);
        CP_COMMIT();
    }

    // halfn -> smem
    for (int k = tid; k < NUM_EMBED; k += MAIN_THREADS)
        sm_halfn[k] = g_halfn[k];

    // ---- A fragments: 2 Mtiles per warp, hi+lo (128 regs) ----
    const int n0 = blockIdx.x * TPC;
    const int bb = n0 >> 15;
    const int s0 = n0 & (SPATIAL - 1);
    const float* xbase = inputs + (size_t)bb * (EMBED_DIM * SPATIAL) + s0;

    uint32_t ahi[2][32], alo[2][32];
    #pragma unroll
    for (int m = 0; m < 2; m++) {
        #pragma unroll
        for (int h = 0; h < 2; h++) {
            const int tok = wid * 32 + m * 16 + h * 8 + g;
            #pragma unroll
            for (int kt = 0; kt < 8; kt++) {
                #pragma unroll
                for (int pp = 0; pp < 2; pp++) {
                    const int c = kt * 8 + q + pp * 4;
                    const float x  = xbase[(size_t)c * SPATIAL + tok];
                    const float hi = tf32f(x);
                    const float lo = tf32f(x - hi);
                    ahi[m][h * 16 + kt * 2 + pp] = __float_as_uint(hi);
                    alo[m][h * 16 + kt * 2 + pp] = __float_as_uint(lo);
                }
            }
        }
    }

    // per-thread argmin state: [m][h] -> token row wid*32+m*16+h*8+g
    float best[2][2] = {{3.4e38f, 3.4e38f}, {3.4e38f, 3.4e38f}};
    int   bidx[2][2] = {{0, 0}, {0, 0}};

    // ---- chunk loop ----
    #pragma unroll 1
    for (int ch = 0; ch < NCHUNK; ch++) {
        CP_WAIT1();
        __syncthreads();
        const float* B = (const float*)(smem_raw + SM_BUF + (ch & 1) * CHUNK_BYTES);

        #pragma unroll 1
        for (int ntp = 0; ntp < 4; ntp++) {          // pairs of 8-code groups
            float d0a[4] = {0.f, 0.f, 0.f, 0.f};     // Mtile0 x ngroup a
            float d1a[4] = {0.f, 0.f, 0.f, 0.f};     // Mtile1 x ngroup a
            float d0b[4] = {0.f, 0.f, 0.f, 0.f};     // Mtile0 x ngroup b
            float d1b[4] = {0.f, 0.f, 0.f, 0.f};     // Mtile1 x ngroup b
            const float* browa = B + (size_t)(ntp * 16 + g)     * PN + q * QS;
            const float* browb = B + (size_t)(ntp * 16 + 8 + g) * PN + q * QS;

            #pragma unroll
            for (int u = 0; u < 12; u++) {
                const float4 bva = *(const float4*)(browa + u * 4);
                const float4 bvb = *(const float4*)(browb + u * 4);
                #pragma unroll
                for (int kk = 0; kk < 2; kk++) {
                    const int kt = 2 * u + kk;       // 0..23, compile-time
                    const uint32_t ba0 = __float_as_uint(kk ? bva.z : bva.x);
                    const uint32_t ba1 = __float_as_uint(kk ? bva.w : bva.y);
                    const uint32_t bb0 = __float_as_uint(kk ? bvb.z : bvb.x);
                    const uint32_t bb1 = __float_as_uint(kk ? bvb.w : bvb.y);
                    const int i0 = (kt & 7) * 2;
                    const bool useLo = (kt >= 8) && (kt < 16);
                    const uint32_t a00 = useLo ? alo[0][i0]      : ahi[0][i0];
                    const uint32_t a01 = useLo ? alo[0][16 + i0] : ahi[0][16 + i0];
                    const uint32_t a02 = useLo ? alo[0][i0 + 1]  : ahi[0][i0 + 1];
                    const uint32_t a03 = useLo ? alo[0][17 + i0] : ahi[0][17 + i0];
                    const uint32_t a10 = useLo ? alo[1][i0]      : ahi[1][i0];
                    const uint32_t a11 = useLo ? alo[1][16 + i0] : ahi[1][16 + i0];
                    const uint32_t a12 = useLo ? alo[1][i0 + 1]  : ahi[1][i0 + 1];
                    const uint32_t a13 = useLo ? alo[1][17 + i0] : ahi[1][17 + i0];
                    mma8(d0a, a00, a01, a02, a03, ba0, ba1);
                    mma8(d1a, a10, a11, a12, a13, ba0, ba1);
                    mma8(d0b, a00, a01, a02, a03, bb0, bb1);
                    mma8(d1b, a10, a11, a12, a13, bb0, bb1);
                }
            }

            // fold; codes ascend across groups -> strict < keeps first min
            const int kba = ch * CC + ntp * 16;
            const int kbb = kba + 8;
            const float2 hna = *(const float2*)(sm_halfn + kba + 2 * q);
            const float2 hnb = *(const float2*)(sm_halfn + kbb + 2 * q);
            const int ca0 = kba + 2 * q, ca1 = ca0 + 1;
            const int cb0 = kbb + 2 * q, cb1 = cb0 + 1;
            float dd;
            dd = hna.x - d0a[0]; if (dd < best[0][0]) { best[0][0] = dd; bidx[0][0] = ca0; }
            dd = hna.y - d0a[1]; if (dd < best[0][0]) { best[0][0] = dd; bidx[0][0] = ca1; }
            dd = hna.x - d0a[2]; if (dd < best[0][1]) { best[0][1] = dd; bidx[0][1] = ca0; }
            dd = hna.y - d0a[3]; if (dd < best[0][1]) { best[0][1] = dd; bidx[0][1] = ca1; }
            dd = hna.x - d1a[0]; if (dd < best[1][0]) { best[1][0] = dd; bidx[1][0] = ca0; }
            dd = hna.y - d1a[1]; if (dd < best[1][0]) { best[1][0] = dd; bidx[1][0] = ca1; }
            dd = hna.x - d1a[2]; if (dd < best[1][1]) { best[1][1] = dd; bidx[1][1] = ca0; }
            dd = hna.y - d1a[3]; if (dd < best[1][1]) { best[1][1] = dd; bidx[1][1] = ca1; }
            dd = hnb.x - d0b[0]; if (dd < best[0][0]) { best[0][0] = dd; bidx[0][0] = cb0; }
            dd = hnb.y - d0b[1]; if (dd < best[0][0]) { best[0][0] = dd; bidx[0][0] = cb1; }
            dd = hnb.x - d0b[2]; if (dd < best[0][1]) { best[0][1] = dd; bidx[0][1] = cb0; }
            dd = hnb.y - d0b[3]; if (dd < best[0][1]) { best[0][1] = dd; bidx[0][1] = cb1; }
            dd = hnb.x - d1b[0]; if (dd < best[1][0]) { best[1][0] = dd; bidx[1][0] = cb0; }
            dd = hnb.y - d1b[1]; if (dd < best[1][0]) { best[1][0] = dd; bidx[1][0] = cb1; }
            dd = hnb.x - d1b[2]; if (dd < best[1][1]) { best[1][1] = dd; bidx[1][1] = cb0; }
            dd = hnb.y - d1b[3]; if (dd < best[1][1]) { best[1][1] = dd; bidx[1][1] = cb1; }
        }

        __syncthreads();   // all warps done with buf[ch&1] before refill
        {
            const int nxt = ch + 2;
            if (nxt < NCHUNK) {
                const char* src = (const char*)g_bpack + (size_t)nxt * CHUNK_BYTES;
                for (int off = tid * 16; off < CHUNK_BYTES; off += MAIN_THREADS * 16)
                    CP_ASYNC16(sb + SM_BUF + (ch & 1) * CHUNK_BYTES + off, src + off);
            }
            CP_COMMIT();   // commit every iteration (possibly empty) to keep counts
        }
    }

    // ---- quad reduction (lanes q=0..3 hold disjoint code subsets) ----
    #pragma unroll
    for (int m = 0; m < 2; m++) {
        #pragma unroll
        for (int h = 0; h < 2; h++) {
            float b = best[m][h];
            int   bi = bidx[m][h];
            #pragma unroll
            for (int delta = 1; delta <= 2; delta <<= 1) {
                const float ob = __shfl_down_sync(0xffffffffu, b, delta, 4);
                const int   oi = __shfl_down_sync(0xffffffffu, bi, delta, 4);
                if (ob < b || (ob == b && oi < bi)) { b = ob; bi = oi; }
            }
            if (q == 0)
                sm_bestk[wid * 32 + m * 16 + h * 8 + g] = bi;
        }
    }
    __syncthreads();

    // ---- exact fp32 epilogue: one token per thread (bit-identical to R3) ----
    {
        const int n = n0 + tid;
        const int k = sm_bestk[tid];
        out[OFF_IDX + n] = (float)k;
        atomicAdd(&g_counts[k], 1.0f);

        const float* er  = embed + (size_t)k * EMBED_DIM;
        const float* xin = xbase + tid;
        float* qout = out + OFF_Q + (size_t)bb * (EMBED_DIM * SPATIAL) + s0 + tid;
        float* dwr  = g_dw + (size_t)k * EMBED_DIM;

        float lsum = 0.0f;
        #pragma unroll 8
        for (int c = 0; c < EMBED_DIM; c++) {
            const float e = er[c];
            const float x = xin[(size_t)c * SPATIAL];
            const float d = e - x;                 // quantized_cf - inputs
            lsum = fmaf(d, d, lsum);
            qout[(size_t)c * SPATIAL] = x + d;     // straight-through rounding
            atomicAdd(&dwr[c], x);
        }
        double la = (double)lsum;
        #pragma unroll
        for (int off = 16; off > 0; off >>= 1)
            la += __shfl_down_sync(0xffffffffu, la, off);
        if (lane == 0) atomicAdd(&g_loss, la);
    }
}

// ---------------------------------------------------------------------------
// Finalize: EMA update, Laplace smoothing, perplexity, loss
// ---------------------------------------------------------------------------
__global__ void __launch_bounds__(NUM_EMBED)
vq_finalize_kernel(const float* __restrict__ embed_avg,
                   const float* __restrict__ cluster_size,
                   float* __restrict__ out)
{
    __shared__ float  s_smoothed[NUM_EMBED];
    __shared__ double s_red[NUM_EMBED];

    const int t = threadIdx.x;

    const float cnt = g_counts[t];
    const float ncs = cluster_size[t] * DECAY + ONE_MINUS_DECAY * cnt;
    out[OFF_CS + t] = ncs;

    s_red[t] = (double)ncs;
    __syncthreads();
    #pragma unroll
    for (int off = NUM_EMBED / 2; off > 0; off >>= 1) {
        if (t < off) s_red[t] += s_red[t + off];
        __syncthreads();
    }
    const float nf = (float)s_red[0];
    __syncthreads();

    s_smoothed[t] = nf * ((ncs + LAPLACE_ALPHA) / (nf + NUM_EMBED * LAPLACE_ALPHA));

    const float p = cnt / (float)N_TOKENS;
    s_red[t] = (double)(p * logf(p + 1e-10f));
    __syncthreads();
    #pragma unroll
    for (int off = NUM_EMBED / 2; off > 0; off >>= 1) {
        if (t < off) s_red[t] += s_red[t + off];
        __syncthreads();
    }
    if (t == 0) {
        out[OFF_PERP] = expf(-(float)s_red[0]);
        out[OFF_LOSS] = COMMIT_COST * (float)(g_loss / (double)Q_ELEMS);
    }
    __syncthreads();

    for (int i = t; i < NUM_EMBED * EMBED_DIM; i += NUM_EMBED) {
        const float ea = embed_avg[i] * DECAY + ONE_MINUS_DECAY * g_dw[i];
        out[OFF_EA + i]       = ea;
        out[OFF_NEWEMBED + i] = ea / s_smoothed[i >> 6];
    }
}

// ---------------------------------------------------------------------------
// Launch
// ---------------------------------------------------------------------------
extern "C" void kernel_launch(void* const* d_in, const int* in_sizes, int n_in,
                              void* d_out, int out_size)
{
    const float* inputs       = (const float*)d_in[0];
    const float* embed        = (const float*)d_in[1];
    const float* embed_avg    = (const float*)d_in[2];
    const float* cluster_size = (const float*)d_in[3];
    float* out = (float*)d_out;

    cudaFuncSetAttribute(vq_main_kernel,
                         cudaFuncAttributeMaxDynamicSharedMemorySize, SMEM_TOTAL);

    vq_zero_kernel<<<(NUM_EMBED * EMBED_DIM + 255) / 256, 256>>>();
    vq_pack_b_kernel<<<(NUM_EMBED * 192 + 255) / 256, 256>>>(embed);
    vq_halfn_kernel<<<1, NUM_EMBED>>>(embed);
    vq_main_kernel<<<MAIN_CTAS, MAIN_THREADS, SMEM_TOTAL>>>(inputs, embed, out);
    vq_finalize_kernel<<<1, NUM_EMBED>>>(embed_avg, cluster_size, out);
}